// round 11
// baseline (speedup 1.0000x reference)
#include <cuda_runtime.h>
#include <cuda_bf16.h>
#include <cstdint>

// ---------------------------------------------------------------------------
// IterativeEmbeddingModel: 2 iterations of
//   emb <- concat(emb@T1, seg_sum(emb[col],row)@T2, seg_sum_anti(...)@T3)
// R11 (vs R8/R10: gemm 60.8us, tensor 33.5%, L1 51.4% -> shared-pipe-bound):
//  - Warp tile m32 x n32 (8 warps / 256 thr, BM=128): B fragments shared
//    across 2x the m-rows -> shared bytes per MMA 256B -> 170B (-33%).
//  - B in fragment-order uint4 smem ({b0h,b1h,b0l,b1l} per lane/tile/kstep,
//    layout verified in R9): one LDS.128 per tile fetches hi+lo.
//  Same split-bf16 3-term math (rel_err ~6e-6, tolerance 1e-3).
// ---------------------------------------------------------------------------

#define NMAX 50000
#define EMAX 400000
#define DIM  192
#define PP   64

// Scratch (device globals; no allocation APIs allowed)
__device__ int      g_count[2 * NMAX];
__device__ int      g_cursor[2 * NMAX];
__device__ int      g_rowstart[2 * (NMAX + 1)];
__device__ int      g_blocksum[2 * 128];
__device__ int      g_cols[2 * EMAX];
__device__ float    g_emb1[(size_t)NMAX * DIM];   // iteration-1 output
__device__ float    g_Y[(size_t)NMAX * 128];      // [Y2 | Y3] per row
__device__ uint4    g_Bfrag[3 * 12 * 8 * 32];     // thetas, fragment-order

__device__ __forceinline__ uint32_t smem_to_u32(const void* p) {
    uint32_t a;
    asm("{ .reg .u64 t; cvta.to.shared.u64 t, %1; cvt.u32.u64 %0, t; }"
        : "=r"(a) : "l"(p));
    return a;
}

// ---- CSR build ------------------------------------------------------------
__global__ void zero_counts_kernel() {
    int i = blockIdx.x * blockDim.x + threadIdx.x;
    if (i < 2 * NMAX) g_count[i] = 0;
}

__global__ void hist_kernel(const int* __restrict__ e0, const int* __restrict__ e1, int nE) {
    int i = blockIdx.x * blockDim.x + threadIdx.x;
    if (i >= 2 * nE) return;
    int l = (i < nE) ? 0 : 1;
    const int* p = l ? e1 : e0;
    int e = l ? (i - nE) : i;
    int d = p[e];
    atomicAdd(&g_count[l * NMAX + d], 1);
}

__global__ void scan_partial_kernel(int n) {
    __shared__ int warp_sums[16];
    int l = blockIdx.y;
    int i = blockIdx.x * 512 + threadIdx.x;
    int lane = threadIdx.x & 31;
    int w = threadIdx.x >> 5;
    int v = (i < n) ? g_count[l * NMAX + i] : 0;
    int s = v;
#pragma unroll
    for (int o = 1; o < 32; o <<= 1) {
        int t = __shfl_up_sync(0xFFFFFFFFu, s, o);
        if (lane >= o) s += t;
    }
    if (lane == 31) warp_sums[w] = s;
    __syncthreads();
    if (w == 0) {
        int ws = (lane < 16) ? warp_sums[lane] : 0;
#pragma unroll
        for (int o = 1; o < 16; o <<= 1) {
            int t = __shfl_up_sync(0xFFFFFFFFu, ws, o);
            if (lane >= o) ws += t;
        }
        if (lane < 16) warp_sums[lane] = ws;
    }
    __syncthreads();
    int base = (w > 0) ? warp_sums[w - 1] : 0;
    if (i < n) g_rowstart[l * (NMAX + 1) + i] = base + s - v;
    if (threadIdx.x == 511) g_blocksum[l * 128 + blockIdx.x] = base + s;
}

__global__ void add_offsets_kernel(int n, int nb) {
    int l = blockIdx.y;
    int i = blockIdx.x * blockDim.x + threadIdx.x;
    __shared__ int sP;
    if (threadIdx.x < 32) {
        int myblk = blockIdx.x >> 1;
        int s = 0;
        for (int b = threadIdx.x; b < myblk; b += 32) s += g_blocksum[l * 128 + b];
#pragma unroll
        for (int o = 16; o; o >>= 1) s += __shfl_xor_sync(0xFFFFFFFFu, s, o);
        if (threadIdx.x == 0) sP = s;
    }
    if (blockIdx.x == 0 && threadIdx.x >= 32 && threadIdx.x < 64) {
        int lane = threadIdx.x - 32;
        int s = 0;
        for (int b = lane; b < nb; b += 32) s += g_blocksum[l * 128 + b];
#pragma unroll
        for (int o = 16; o; o >>= 1) s += __shfl_xor_sync(0xFFFFFFFFu, s, o);
        if (lane == 0) g_rowstart[l * (NMAX + 1) + n] = s;
    }
    __syncthreads();
    if (i < n) {
        g_rowstart[l * (NMAX + 1) + i] += sP;
        g_cursor[l * NMAX + i] = 0;
    }
}

__global__ void fill_kernel(const int* __restrict__ e0, const int* __restrict__ e1, int nE) {
    int i = blockIdx.x * blockDim.x + threadIdx.x;
    if (i >= 2 * nE) return;
    int l = (i < nE) ? 0 : 1;
    const int* p = l ? e1 : e0;
    int e = l ? (i - nE) : i;
    int d = p[e];
    int c = p[nE + e];
    int pos = g_rowstart[l * (NMAX + 1) + d] + atomicAdd(&g_cursor[l * NMAX + d], 1);
    g_cols[l * EMAX + pos] = c;
}

// ---- Theta conversion (once): fp32 [192,64] -> fragment-order bf16 hi/lo --
// g_Bfrag[tt][ks][tile][lane] = {b0h, b1h, b0l, b1l}  (verified in R9)
__global__ void convert_theta_kernel(const float* __restrict__ t1,
                                     const float* __restrict__ t2,
                                     const float* __restrict__ t3) {
    int i = blockIdx.x * blockDim.x + threadIdx.x;
    if (i >= 3 * 12 * 8 * 32) return;
    int tt = i / 3072;
    int r = i % 3072;
    int ks = r >> 8;            // k16 step (0..11)
    int j  = (r >> 5) & 7;      // n8 tile (0..7)
    int l  = r & 31;            // lane
    int g = l >> 2, q = l & 3;
    int nn = j * 8 + g;
    int k0 = ks * 16 + 2 * q;
    const float* T = (tt == 0) ? t1 : (tt == 1) ? t2 : t3;
    float x0 = T[(size_t)k0 * 64 + nn];
    float x1 = T[(size_t)(k0 + 1) * 64 + nn];
    float y0 = T[(size_t)(k0 + 8) * 64 + nn];
    float y1 = T[(size_t)(k0 + 9) * 64 + nn];
    __nv_bfloat162 b0h = __floats2bfloat162_rn(x0, x1);
    __nv_bfloat162 b1h = __floats2bfloat162_rn(y0, y1);
    __nv_bfloat162 b0l = __floats2bfloat162_rn(x0 - __low2float(b0h),
                                               x1 - __high2float(b0h));
    __nv_bfloat162 b1l = __floats2bfloat162_rn(y0 - __low2float(b1h),
                                               y1 - __high2float(b1h));
    g_Bfrag[i] = make_uint4(*(uint32_t*)&b0h, *(uint32_t*)&b1h,
                            *(uint32_t*)&b0l, *(uint32_t*)&b1l);
}

// ---- mma.sync GEMM --------------------------------------------------------
// Per CTA: rows [rowBase, rowBase+128), all 192 output cols (3 thetas).
// 256 threads / 8 warps: warp (w&3) -> m32 group, (w>>2) -> n32 half.
// smem: Ah[128][200] bf16 | Al[128][200] bf16 | Bfrag[12][8][32] uint4
#define A_STRIDE 200
#define OFF_AH 0
#define OFF_AL 51200
#define OFF_BF 102400
#define GEMM_SMEM_BYTES 151552

#define MMA(C, A0, A1, A2, A3, B0, B1)                                  \
    asm("mma.sync.aligned.m16n8k16.row.col.f32.bf16.bf16.f32 "          \
        "{%0,%1,%2,%3}, {%4,%5,%6,%7}, {%8,%9}, {%0,%1,%2,%3};"         \
        : "+f"(C.x), "+f"(C.y), "+f"(C.z), "+f"(C.w)                    \
        : "r"(A0), "r"(A1), "r"(A2), "r"(A3), "r"(B0), "r"(B1))

#define LDMX4(R0, R1, R2, R3, ADDR)                                     \
    asm volatile("ldmatrix.sync.aligned.m8n8.x4.shared.b16 "            \
                 "{%0,%1,%2,%3}, [%4];"                                 \
                 : "=r"(R0), "=r"(R1), "=r"(R2), "=r"(R3) : "r"(ADDR))

__global__ __launch_bounds__(256, 1)
void gemm_kernel(const float* __restrict__ A,
                 float* __restrict__ dst,   // n x 192 (theta0 -> cols 0:64)
                 float* __restrict__ Y,     // n x 128 (theta1|theta2)
                 int n)
{
    extern __shared__ char smem[];
    uint32_t* Ah32 = (uint32_t*)(smem + OFF_AH);
    uint32_t* Al32 = (uint32_t*)(smem + OFF_AL);
    uint4*    Bs   = (uint4*)(smem + OFF_BF);

    const int tid = threadIdx.x;
    const int w = tid >> 5;
    const int lane = tid & 31;
    const int mw = w & 3;          // m32 row-group index
    const int nh = w >> 2;         // n half (tiles nh*4 .. nh*4+3)
    const int q = lane & 3;
    const int rowBase = blockIdx.x * 128;

    // ---- Convert A rows to bf16 hi/lo in smem (coalesced, conflict-free) --
    for (int f = tid; f < 128 * 96; f += 256) {
        int r = f / 96, k2 = f % 96;
        int gr = rowBase + r;
        float2 v = make_float2(0.f, 0.f);
        if (gr < n) v = *(const float2*)(A + (size_t)gr * DIM + 2 * k2);
        __nv_bfloat162 hh = __floats2bfloat162_rn(v.x, v.y);
        float r0 = v.x - __low2float(hh);
        float r1 = v.y - __high2float(hh);
        __nv_bfloat162 ll = __floats2bfloat162_rn(r0, r1);
        Ah32[r * 100 + k2] = *(uint32_t*)&hh;
        Al32[r * 100 + k2] = *(uint32_t*)&ll;
    }

    // ---- per-lane ldmatrix A base addresses (two m16 groups) ----
    const uint32_t sb = smem_to_u32(smem);
    const int raA = (lane & 7) + ((lane >> 3) & 1) * 8;
    const int kaA = ((lane >> 4) & 1) * 8;
    uint32_t aAh0 = sb + OFF_AH + (uint32_t)((mw * 32 + raA) * A_STRIDE + kaA) * 2;
    uint32_t aAh1 = aAh0 + 16 * A_STRIDE * 2;
    uint32_t aAl0 = aAh0 + (OFF_AL - OFF_AH);
    uint32_t aAl1 = aAh1 + (OFF_AL - OFF_AH);

    // B fragment smem base for this warp's four tiles
    const uint4* Bq = Bs + (nh * 4) * 32 + lane;   // + ks*256; + J*32 per tile

    const int row0 = rowBase + mw * 32 + (lane >> 2);   // m-group 0
    const int row2 = row0 + 16;                         // m-group 1

#pragma unroll
    for (int tt = 0; tt < 3; ++tt) {
        __syncthreads();   // previous theta's B readers done (and A ready)
        {
            const uint4* gB = g_Bfrag + tt * 3072;
            for (int f = tid; f < 3072; f += 256) Bs[f] = gB[f];
        }
        __syncthreads();

        float4 d0 = make_float4(0.f, 0.f, 0.f, 0.f), d1 = d0, d2 = d0, d3 = d0;
        float4 e0 = d0, e1 = d0, e2 = d0, e3 = d0;

#pragma unroll 2
        for (int ks = 0; ks < 12; ++ks) {
            const uint32_t ko = (uint32_t)ks * 32;   // 16 bf16 = 32 bytes
            uint32_t ah00, ah01, ah02, ah03, ah10, ah11, ah12, ah13;
            uint32_t al00, al01, al02, al03, al10, al11, al12, al13;
            LDMX4(ah00, ah01, ah02, ah03, aAh0 + ko);
            LDMX4(ah10, ah11, ah12, ah13, aAh1 + ko);
            LDMX4(al00, al01, al02, al03, aAl0 + ko);
            LDMX4(al10, al11, al12, al13, aAl1 + ko);
            uint4 B0 = Bq[ks * 256];
            uint4 B1 = Bq[ks * 256 + 32];
            uint4 B2 = Bq[ks * 256 + 64];
            uint4 B3 = Bq[ks * 256 + 96];

            // hi_A x hi_B
            MMA(d0, ah00, ah01, ah02, ah03, B0.x, B0.y);
            MMA(e0, ah10, ah11, ah12, ah13, B0.x, B0.y);
            MMA(d1, ah00, ah01, ah02, ah03, B1.x, B1.y);
            MMA(e1, ah10, ah11, ah12, ah13, B1.x, B1.y);
            MMA(d2, ah00, ah01, ah02, ah03, B2.x, B2.y);
            MMA(e2, ah10, ah11, ah12, ah13, B2.x, B2.y);
            MMA(d3, ah00, ah01, ah02, ah03, B3.x, B3.y);
            MMA(e3, ah10, ah11, ah12, ah13, B3.x, B3.y);
            // hi_A x lo_B
            MMA(d0, ah00, ah01, ah02, ah03, B0.z, B0.w);
            MMA(e0, ah10, ah11, ah12, ah13, B0.z, B0.w);
            MMA(d1, ah00, ah01, ah02, ah03, B1.z, B1.w);
            MMA(e1, ah10, ah11, ah12, ah13, B1.z, B1.w);
            MMA(d2, ah00, ah01, ah02, ah03, B2.z, B2.w);
            MMA(e2, ah10, ah11, ah12, ah13, B2.z, B2.w);
            MMA(d3, ah00, ah01, ah02, ah03, B3.z, B3.w);
            MMA(e3, ah10, ah11, ah12, ah13, B3.z, B3.w);
            // lo_A x hi_B
            MMA(d0, al00, al01, al02, al03, B0.x, B0.y);
            MMA(e0, al10, al11, al12, al13, B0.x, B0.y);
            MMA(d1, al00, al01, al02, al03, B1.x, B1.y);
            MMA(e1, al10, al11, al12, al13, B1.x, B1.y);
            MMA(d2, al00, al01, al02, al03, B2.x, B2.y);
            MMA(e2, al10, al11, al12, al13, B2.x, B2.y);
            MMA(d3, al00, al01, al02, al03, B3.x, B3.y);
            MMA(e3, al10, al11, al12, al13, B3.x, B3.y);
        }

        // ---- Epilogue for this theta ----
        float* outp = (tt == 0) ? dst : Y;
        const int ostr = (tt == 0) ? DIM : 128;
        const int cb = ((tt == 2) ? 64 : 0) + nh * 32;
#define ST_TILE(C, J, R0)                                                     \
        {                                                                     \
            int col = cb + (J) * 8 + 2 * q;                                   \
            if ((R0) < n)                                                     \
                *(float2*)(outp + (size_t)(R0) * ostr + col) =                \
                    make_float2(C.x, C.y);                                    \
            if ((R0) + 8 < n)                                                 \
                *(float2*)(outp + (size_t)((R0) + 8) * ostr + col) =          \
                    make_float2(C.z, C.w);                                    \
        }
        ST_TILE(d0, 0, row0) ST_TILE(d1, 1, row0) ST_TILE(d2, 2, row0) ST_TILE(d3, 3, row0)
        ST_TILE(e0, 0, row2) ST_TILE(e1, 1, row2) ST_TILE(e2, 2, row2) ST_TILE(e3, 3, row2)
#undef ST_TILE
    }
}

// ---- Aggregation: warp per node, atomic-free CSR gather -------------------
__global__ void agg_kernel(const float* __restrict__ Y, float* __restrict__ dst, int n)
{
    int gw = (blockIdx.x * blockDim.x + threadIdx.x) >> 5;
    int lane = threadIdx.x & 31;
    if (gw >= n) return;
#pragma unroll
    for (int l = 0; l < 2; ++l) {
        const int* rs = g_rowstart + l * (NMAX + 1);
        const int* cs = g_cols + l * EMAX;
        int s = __ldg(rs + gw);
        int e = __ldg(rs + gw + 1);
        const float* Yb = Y + l * 64 + lane * 2;
        float ax = 0.f, ay = 0.f;
        int j = s;
        for (; j + 4 <= e; j += 4) {
            int c0 = cs[j], c1 = cs[j + 1], c2 = cs[j + 2], c3 = cs[j + 3];
            float2 v0 = *(const float2*)(Yb + (size_t)c0 * 128);
            float2 v1 = *(const float2*)(Yb + (size_t)c1 * 128);
            float2 v2 = *(const float2*)(Yb + (size_t)c2 * 128);
            float2 v3 = *(const float2*)(Yb + (size_t)c3 * 128);
            ax += (v0.x + v1.x) + (v2.x + v3.x);
            ay += (v0.y + v1.y) + (v2.y + v3.y);
        }
        for (; j < e; ++j) {
            float2 v = *(const float2*)(Yb + (size_t)cs[j] * 128);
            ax += v.x; ay += v.y;
        }
        float2 o = make_float2(ax, ay);
        *(float2*)(dst + (size_t)gw * DIM + 64 + l * 64 + lane * 2) = o;
    }
}

// ---------------------------------------------------------------------------
extern "C" void kernel_launch(void* const* d_in, const int* in_sizes, int n_in,
                              void* d_out, int out_size)
{
    const float* emb = (const float*)d_in[0];
    const float* t1  = (const float*)d_in[1];
    const float* t2  = (const float*)d_in[2];
    const float* t3  = (const float*)d_in[3];
    const int*   e0  = (const int*)d_in[4];
    const int*   e1  = (const int*)d_in[5];

    int n  = in_sizes[0] / DIM;
    int nE = in_sizes[4] / 2;
    float* out = (float*)d_out;

    void *p_emb1_v, *p_Y_v;
    cudaGetSymbolAddress(&p_emb1_v, g_emb1);
    cudaGetSymbolAddress(&p_Y_v, g_Y);
    float* p_emb1 = (float*)p_emb1_v;
    float* p_Y    = (float*)p_Y_v;

    cudaFuncSetAttribute(gemm_kernel, cudaFuncAttributeMaxDynamicSharedMemorySize,
                         GEMM_SMEM_BYTES);

    int nb = (n + 511) / 512;
    int gemm_blocks = (n + 127) / 128;
    int agg_blocks = (n * 32 + 255) / 256;

    // gemm1 at launch slot #4 (the slot ncu captures) for profiling.
    zero_counts_kernel<<<(2 * NMAX + 255) / 256, 256>>>();                 // 1
    hist_kernel<<<(2 * nE + 255) / 256, 256>>>(e0, e1, nE);                // 2
    convert_theta_kernel<<<(3 * 12 * 8 * 32 + 255) / 256, 256>>>(t1, t2, t3); // 3
    gemm_kernel<<<gemm_blocks, 256, GEMM_SMEM_BYTES>>>(emb, p_emb1, p_Y, n); // 4
    dim3 gscan(nb, 2);
    scan_partial_kernel<<<gscan, 512>>>(n);                                // 5
    dim3 goff((n + 255) / 256, 2);
    add_offsets_kernel<<<goff, 256>>>(n, nb);                              // 6
    fill_kernel<<<(2 * nE + 255) / 256, 256>>>(e0, e1, nE);                // 7
    agg_kernel<<<agg_blocks, 256>>>(p_Y, p_emb1, n);                       // 8
    gemm_kernel<<<gemm_blocks, 256, GEMM_SMEM_BYTES>>>(p_emb1, out, p_Y, n); // 9
    agg_kernel<<<agg_blocks, 256>>>(p_Y, out, n);                          // 10
}

// round 12
// speedup vs baseline: 1.0764x; 1.0764x over previous
#include <cuda_runtime.h>
#include <cuda_bf16.h>
#include <cstdint>

// ---------------------------------------------------------------------------
// IterativeEmbeddingModel: 2 iterations of
//   emb <- concat(emb@T1, seg_sum(emb[col],row)@T2, seg_sum_anti(...)@T3)
// R12 (synthesis of R8/R9/R10/R11 measurements):
//   throughput = min(shared-pipe, warps x ILP). R8: 16 warps but 256B/MMA
//   (L1 51% wall). R11: 170B/MMA but 8 warps (latency wall). R12 gets BOTH:
//   phase A processes theta0+theta1 as ONE n=128 tile -> 16 warps each with
//   an m32xn32 tile (170B/MMA). Theta2 = short phase B (m32xn16).
//   BM=128, 512 thr, smem 200.7KB, frag-order B, split-bf16 3-term.
// ---------------------------------------------------------------------------

#define NMAX 50000
#define EMAX 400000
#define DIM  192
#define PP   64

// Scratch (device globals; no allocation APIs allowed)
__device__ int      g_count[2 * NMAX];
__device__ int      g_cursor[2 * NMAX];
__device__ int      g_rowstart[2 * (NMAX + 1)];
__device__ int      g_blocksum[2 * 128];
__device__ int      g_cols[2 * EMAX];
__device__ float    g_emb1[(size_t)NMAX * DIM];   // iteration-1 output
__device__ float    g_Y[(size_t)NMAX * 128];      // [Y2 | Y3] per row
__device__ uint4    g_Bfrag[3 * 12 * 8 * 32];     // thetas, fragment-order

__device__ __forceinline__ uint32_t smem_to_u32(const void* p) {
    uint32_t a;
    asm("{ .reg .u64 t; cvta.to.shared.u64 t, %1; cvt.u32.u64 %0, t; }"
        : "=r"(a) : "l"(p));
    return a;
}

// ---- CSR build ------------------------------------------------------------
__global__ void zero_counts_kernel() {
    int i = blockIdx.x * blockDim.x + threadIdx.x;
    if (i < 2 * NMAX) g_count[i] = 0;
}

__global__ void hist_kernel(const int* __restrict__ e0, const int* __restrict__ e1, int nE) {
    int i = blockIdx.x * blockDim.x + threadIdx.x;
    if (i >= 2 * nE) return;
    int l = (i < nE) ? 0 : 1;
    const int* p = l ? e1 : e0;
    int e = l ? (i - nE) : i;
    int d = p[e];
    atomicAdd(&g_count[l * NMAX + d], 1);
}

__global__ void scan_partial_kernel(int n) {
    __shared__ int warp_sums[16];
    int l = blockIdx.y;
    int i = blockIdx.x * 512 + threadIdx.x;
    int lane = threadIdx.x & 31;
    int w = threadIdx.x >> 5;
    int v = (i < n) ? g_count[l * NMAX + i] : 0;
    int s = v;
#pragma unroll
    for (int o = 1; o < 32; o <<= 1) {
        int t = __shfl_up_sync(0xFFFFFFFFu, s, o);
        if (lane >= o) s += t;
    }
    if (lane == 31) warp_sums[w] = s;
    __syncthreads();
    if (w == 0) {
        int ws = (lane < 16) ? warp_sums[lane] : 0;
#pragma unroll
        for (int o = 1; o < 16; o <<= 1) {
            int t = __shfl_up_sync(0xFFFFFFFFu, ws, o);
            if (lane >= o) ws += t;
        }
        if (lane < 16) warp_sums[lane] = ws;
    }
    __syncthreads();
    int base = (w > 0) ? warp_sums[w - 1] : 0;
    if (i < n) g_rowstart[l * (NMAX + 1) + i] = base + s - v;
    if (threadIdx.x == 511) g_blocksum[l * 128 + blockIdx.x] = base + s;
}

__global__ void add_offsets_kernel(int n, int nb) {
    int l = blockIdx.y;
    int i = blockIdx.x * blockDim.x + threadIdx.x;
    __shared__ int sP;
    if (threadIdx.x < 32) {
        int myblk = blockIdx.x >> 1;
        int s = 0;
        for (int b = threadIdx.x; b < myblk; b += 32) s += g_blocksum[l * 128 + b];
#pragma unroll
        for (int o = 16; o; o >>= 1) s += __shfl_xor_sync(0xFFFFFFFFu, s, o);
        if (threadIdx.x == 0) sP = s;
    }
    if (blockIdx.x == 0 && threadIdx.x >= 32 && threadIdx.x < 64) {
        int lane = threadIdx.x - 32;
        int s = 0;
        for (int b = lane; b < nb; b += 32) s += g_blocksum[l * 128 + b];
#pragma unroll
        for (int o = 16; o; o >>= 1) s += __shfl_xor_sync(0xFFFFFFFFu, s, o);
        if (lane == 0) g_rowstart[l * (NMAX + 1) + n] = s;
    }
    __syncthreads();
    if (i < n) {
        g_rowstart[l * (NMAX + 1) + i] += sP;
        g_cursor[l * NMAX + i] = 0;
    }
}

__global__ void fill_kernel(const int* __restrict__ e0, const int* __restrict__ e1, int nE) {
    int i = blockIdx.x * blockDim.x + threadIdx.x;
    if (i >= 2 * nE) return;
    int l = (i < nE) ? 0 : 1;
    const int* p = l ? e1 : e0;
    int e = l ? (i - nE) : i;
    int d = p[e];
    int c = p[nE + e];
    int pos = g_rowstart[l * (NMAX + 1) + d] + atomicAdd(&g_cursor[l * NMAX + d], 1);
    g_cols[l * EMAX + pos] = c;
}

// ---- Theta conversion (once): fp32 [192,64] -> fragment-order bf16 hi/lo --
// g_Bfrag[tt][ks][tile][lane] = {b0h, b1h, b0l, b1l}  (layout verified R9/R11)
__global__ void convert_theta_kernel(const float* __restrict__ t1,
                                     const float* __restrict__ t2,
                                     const float* __restrict__ t3) {
    int i = blockIdx.x * blockDim.x + threadIdx.x;
    if (i >= 3 * 12 * 8 * 32) return;
    int tt = i / 3072;
    int r = i % 3072;
    int ks = r >> 8;            // k16 step (0..11)
    int j  = (r >> 5) & 7;      // n8 tile (0..7)
    int l  = r & 31;            // lane
    int g = l >> 2, q = l & 3;
    int nn = j * 8 + g;
    int k0 = ks * 16 + 2 * q;
    const float* T = (tt == 0) ? t1 : (tt == 1) ? t2 : t3;
    float x0 = T[(size_t)k0 * 64 + nn];
    float x1 = T[(size_t)(k0 + 1) * 64 + nn];
    float y0 = T[(size_t)(k0 + 8) * 64 + nn];
    float y1 = T[(size_t)(k0 + 9) * 64 + nn];
    __nv_bfloat162 b0h = __floats2bfloat162_rn(x0, x1);
    __nv_bfloat162 b1h = __floats2bfloat162_rn(y0, y1);
    __nv_bfloat162 b0l = __floats2bfloat162_rn(x0 - __low2float(b0h),
                                               x1 - __high2float(b0h));
    __nv_bfloat162 b1l = __floats2bfloat162_rn(y0 - __low2float(b1h),
                                               y1 - __high2float(b1h));
    g_Bfrag[i] = make_uint4(*(uint32_t*)&b0h, *(uint32_t*)&b1h,
                            *(uint32_t*)&b0l, *(uint32_t*)&b1l);
}

// ---- mma.sync GEMM --------------------------------------------------------
// Per CTA: rows [rowBase, rowBase+128), 512 threads / 16 warps.
// Phase A: theta0+theta1 as one n=128 tile. warp (w&3)->m32 group,
//          (w>>2)->n32 group over 16 n8-tiles. Layout Bs[ks][16 tiles][32].
// Phase B: theta2 (n=64). warp (w>>2)->n16 group. Layout Bs[ks][8 tiles][32].
// smem: Ah[128][200] | Al[128][200] | B frag region (max 98304B)
#define A_STRIDE 200
#define OFF_AH 0
#define OFF_AL 51200
#define OFF_BF 102400
#define GEMM_SMEM_BYTES 200704

#define MMA(C, A0, A1, A2, A3, B0, B1)                                  \
    asm("mma.sync.aligned.m16n8k16.row.col.f32.bf16.bf16.f32 "          \
        "{%0,%1,%2,%3}, {%4,%5,%6,%7}, {%8,%9}, {%0,%1,%2,%3};"         \
        : "+f"(C.x), "+f"(C.y), "+f"(C.z), "+f"(C.w)                    \
        : "r"(A0), "r"(A1), "r"(A2), "r"(A3), "r"(B0), "r"(B1))

#define LDMX4(R0, R1, R2, R3, ADDR)                                     \
    asm volatile("ldmatrix.sync.aligned.m8n8.x4.shared.b16 "            \
                 "{%0,%1,%2,%3}, [%4];"                                 \
                 : "=r"(R0), "=r"(R1), "=r"(R2), "=r"(R3) : "r"(ADDR))

__global__ __launch_bounds__(512, 1)
void gemm_kernel(const float* __restrict__ A,
                 float* __restrict__ dst,   // n x 192 (theta0 -> cols 0:64)
                 float* __restrict__ Y,     // n x 128 (theta1|theta2)
                 int n)
{
    extern __shared__ char smem[];
    uint32_t* Ah32 = (uint32_t*)(smem + OFF_AH);
    uint32_t* Al32 = (uint32_t*)(smem + OFF_AL);
    uint4*    Bs   = (uint4*)(smem + OFF_BF);

    const int tid = threadIdx.x;
    const int w = tid >> 5;
    const int lane = tid & 31;
    const int mw = w & 3;          // m32 row-group index
    const int ng = w >> 2;         // phase A: n32 group (0..3) over 128 cols
    const int q = lane & 3;
    const int rowBase = blockIdx.x * 128;

    // ---- Convert A rows to bf16 hi/lo in smem (coalesced, conflict-free) --
    for (int f = tid; f < 128 * 96; f += 512) {
        int r = f / 96, k2 = f % 96;
        int gr = rowBase + r;
        float2 v = make_float2(0.f, 0.f);
        if (gr < n) v = *(const float2*)(A + (size_t)gr * DIM + 2 * k2);
        __nv_bfloat162 hh = __floats2bfloat162_rn(v.x, v.y);
        float r0 = v.x - __low2float(hh);
        float r1 = v.y - __high2float(hh);
        __nv_bfloat162 ll = __floats2bfloat162_rn(r0, r1);
        Ah32[r * 100 + k2] = *(uint32_t*)&hh;
        Al32[r * 100 + k2] = *(uint32_t*)&ll;
    }

    // ---- Phase A B fill: theta0 -> tiles 0-7, theta1 -> tiles 8-15 ----
    // src g_Bfrag[tt][ks][j][lane] -> dst Bs[ks*512 + tt*256 + j*32 + lane]
    for (int f = tid; f < 6144; f += 512) {
        int tt = f / 3072;
        int r = f % 3072;
        int ks = r >> 8;
        int rest = r & 255;
        Bs[ks * 512 + tt * 256 + rest] = g_Bfrag[f];
    }

    // ---- per-lane ldmatrix A base addresses (two m16 groups) ----
    const uint32_t sb = smem_to_u32(smem);
    const int raA = (lane & 7) + ((lane >> 3) & 1) * 8;
    const int kaA = ((lane >> 4) & 1) * 8;
    uint32_t aAh0 = sb + OFF_AH + (uint32_t)((mw * 32 + raA) * A_STRIDE + kaA) * 2;
    uint32_t aAh1 = aAh0 + 16 * A_STRIDE * 2;
    uint32_t aAl0 = aAh0 + (OFF_AL - OFF_AH);
    uint32_t aAl1 = aAh1 + (OFF_AL - OFF_AH);

    const int row0 = rowBase + mw * 32 + (lane >> 2);   // m-group 0
    const int row2 = row0 + 16;                         // m-group 1

    __syncthreads();

    // ================= Phase A: theta0 + theta1 (n = 128) =================
    {
        const uint4* Bq = Bs + ng * 4 * 32 + lane;      // tiles ng*4..ng*4+3

        float4 d0 = make_float4(0.f, 0.f, 0.f, 0.f), d1 = d0, d2 = d0, d3 = d0;
        float4 e0 = d0, e1 = d0, e2 = d0, e3 = d0;

#pragma unroll 2
        for (int ks = 0; ks < 12; ++ks) {
            const uint32_t ko = (uint32_t)ks * 32;
            uint32_t ah00, ah01, ah02, ah03, ah10, ah11, ah12, ah13;
            uint32_t al00, al01, al02, al03, al10, al11, al12, al13;
            LDMX4(ah00, ah01, ah02, ah03, aAh0 + ko);
            LDMX4(ah10, ah11, ah12, ah13, aAh1 + ko);
            LDMX4(al00, al01, al02, al03, aAl0 + ko);
            LDMX4(al10, al11, al12, al13, aAl1 + ko);
            uint4 B0 = Bq[ks * 512];
            uint4 B1 = Bq[ks * 512 + 32];
            uint4 B2 = Bq[ks * 512 + 64];
            uint4 B3 = Bq[ks * 512 + 96];

            MMA(d0, ah00, ah01, ah02, ah03, B0.x, B0.y);
            MMA(e0, ah10, ah11, ah12, ah13, B0.x, B0.y);
            MMA(d1, ah00, ah01, ah02, ah03, B1.x, B1.y);
            MMA(e1, ah10, ah11, ah12, ah13, B1.x, B1.y);
            MMA(d2, ah00, ah01, ah02, ah03, B2.x, B2.y);
            MMA(e2, ah10, ah11, ah12, ah13, B2.x, B2.y);
            MMA(d3, ah00, ah01, ah02, ah03, B3.x, B3.y);
            MMA(e3, ah10, ah11, ah12, ah13, B3.x, B3.y);
            MMA(d0, ah00, ah01, ah02, ah03, B0.z, B0.w);
            MMA(e0, ah10, ah11, ah12, ah13, B0.z, B0.w);
            MMA(d1, ah00, ah01, ah02, ah03, B1.z, B1.w);
            MMA(e1, ah10, ah11, ah12, ah13, B1.z, B1.w);
            MMA(d2, ah00, ah01, ah02, ah03, B2.z, B2.w);
            MMA(e2, ah10, ah11, ah12, ah13, B2.z, B2.w);
            MMA(d3, ah00, ah01, ah02, ah03, B3.z, B3.w);
            MMA(e3, ah10, ah11, ah12, ah13, B3.z, B3.w);
            MMA(d0, al00, al01, al02, al03, B0.x, B0.y);
            MMA(e0, al10, al11, al12, al13, B0.x, B0.y);
            MMA(d1, al00, al01, al02, al03, B1.x, B1.y);
            MMA(e1, al10, al11, al12, al13, B1.x, B1.y);
            MMA(d2, al00, al01, al02, al03, B2.x, B2.y);
            MMA(e2, al10, al11, al12, al13, B2.x, B2.y);
            MMA(d3, al00, al01, al02, al03, B3.x, B3.y);
            MMA(e3, al10, al11, al12, al13, B3.x, B3.y);
        }

        // ---- Phase A epilogue: tiles 0-7 -> dst (theta0), 8-15 -> Y (theta1)
#define ST_A(C, J, R0)                                                        \
        {                                                                     \
            int gt = ng * 4 + (J);                                            \
            float* outp = (gt < 8) ? dst : Y;                                 \
            int ostr = (gt < 8) ? DIM : 128;                                  \
            int col = ((gt < 8) ? gt * 8 : (gt - 8) * 8) + 2 * q;             \
            if ((R0) < n)                                                     \
                *(float2*)(outp + (size_t)(R0) * ostr + col) =                \
                    make_float2(C.x, C.y);                                    \
            if ((R0) + 8 < n)                                                 \
                *(float2*)(outp + (size_t)((R0) + 8) * ostr + col) =          \
                    make_float2(C.z, C.w);                                    \
        }
        ST_A(d0, 0, row0) ST_A(d1, 1, row0) ST_A(d2, 2, row0) ST_A(d3, 3, row0)
        ST_A(e0, 0, row2) ST_A(e1, 1, row2) ST_A(e2, 2, row2) ST_A(e3, 3, row2)
#undef ST_A
    }

    // ================= Phase B: theta2 (n = 64) =================
    __syncthreads();   // phase A B reads done before overwrite
    {
        const uint4* gB2 = g_Bfrag + 2 * 3072;
        for (int f = tid; f < 3072; f += 512) Bs[f] = gB2[f];
    }
    __syncthreads();
    {
        const int nq = w >> 2;                          // n16 group (0..3)
        const uint4* Bq = Bs + nq * 2 * 32 + lane;      // tiles nq*2, nq*2+1

        float4 d0 = make_float4(0.f, 0.f, 0.f, 0.f), d1 = d0;
        float4 e0 = d0, e1 = d0;

#pragma unroll 3
        for (int ks = 0; ks < 12; ++ks) {
            const uint32_t ko = (uint32_t)ks * 32;
            uint32_t ah00, ah01, ah02, ah03, ah10, ah11, ah12, ah13;
            uint32_t al00, al01, al02, al03, al10, al11, al12, al13;
            LDMX4(ah00, ah01, ah02, ah03, aAh0 + ko);
            LDMX4(ah10, ah11, ah12, ah13, aAh1 + ko);
            LDMX4(al00, al01, al02, al03, aAl0 + ko);
            LDMX4(al10, al11, al12, al13, aAl1 + ko);
            uint4 B0 = Bq[ks * 256];
            uint4 B1 = Bq[ks * 256 + 32];

            MMA(d0, ah00, ah01, ah02, ah03, B0.x, B0.y);
            MMA(e0, ah10, ah11, ah12, ah13, B0.x, B0.y);
            MMA(d1, ah00, ah01, ah02, ah03, B1.x, B1.y);
            MMA(e1, ah10, ah11, ah12, ah13, B1.x, B1.y);
            MMA(d0, ah00, ah01, ah02, ah03, B0.z, B0.w);
            MMA(e0, ah10, ah11, ah12, ah13, B0.z, B0.w);
            MMA(d1, ah00, ah01, ah02, ah03, B1.z, B1.w);
            MMA(e1, ah10, ah11, ah12, ah13, B1.z, B1.w);
            MMA(d0, al00, al01, al02, al03, B0.x, B0.y);
            MMA(e0, al10, al11, al12, al13, B0.x, B0.y);
            MMA(d1, al00, al01, al02, al03, B1.x, B1.y);
            MMA(e1, al10, al11, al12, al13, B1.x, B1.y);
        }

        // ---- Phase B epilogue: theta2 -> Y cols 64:128
#define ST_B(C, J, R0)                                                        \
        {                                                                     \
            int col = 64 + (nq * 2 + (J)) * 8 + 2 * q;                        \
            if ((R0) < n)                                                     \
                *(float2*)(Y + (size_t)(R0) * 128 + col) =                    \
                    make_float2(C.x, C.y);                                    \
            if ((R0) + 8 < n)                                                 \
                *(float2*)(Y + (size_t)((R0) + 8) * 128 + col) =              \
                    make_float2(C.z, C.w);                                    \
        }
        ST_B(d0, 0, row0) ST_B(d1, 1, row0)
        ST_B(e0, 0, row2) ST_B(e1, 1, row2)
#undef ST_B
    }
}

// ---- Aggregation: warp per node, atomic-free CSR gather -------------------
__global__ void agg_kernel(const float* __restrict__ Y, float* __restrict__ dst, int n)
{
    int gw = (blockIdx.x * blockDim.x + threadIdx.x) >> 5;
    int lane = threadIdx.x & 31;
    if (gw >= n) return;
#pragma unroll
    for (int l = 0; l < 2; ++l) {
        const int* rs = g_rowstart + l * (NMAX + 1);
        const int* cs = g_cols + l * EMAX;
        int s = __ldg(rs + gw);
        int e = __ldg(rs + gw + 1);
        const float* Yb = Y + l * 64 + lane * 2;
        float ax = 0.f, ay = 0.f;
        int j = s;
        for (; j + 4 <= e; j += 4) {
            int c0 = cs[j], c1 = cs[j + 1], c2 = cs[j + 2], c3 = cs[j + 3];
            float2 v0 = *(const float2*)(Yb + (size_t)c0 * 128);
            float2 v1 = *(const float2*)(Yb + (size_t)c1 * 128);
            float2 v2 = *(const float2*)(Yb + (size_t)c2 * 128);
            float2 v3 = *(const float2*)(Yb + (size_t)c3 * 128);
            ax += (v0.x + v1.x) + (v2.x + v3.x);
            ay += (v0.y + v1.y) + (v2.y + v3.y);
        }
        for (; j < e; ++j) {
            float2 v = *(const float2*)(Yb + (size_t)cs[j] * 128);
            ax += v.x; ay += v.y;
        }
        float2 o = make_float2(ax, ay);
        *(float2*)(dst + (size_t)gw * DIM + 64 + l * 64 + lane * 2) = o;
    }
}

// ---------------------------------------------------------------------------
extern "C" void kernel_launch(void* const* d_in, const int* in_sizes, int n_in,
                              void* d_out, int out_size)
{
    const float* emb = (const float*)d_in[0];
    const float* t1  = (const float*)d_in[1];
    const float* t2  = (const float*)d_in[2];
    const float* t3  = (const float*)d_in[3];
    const int*   e0  = (const int*)d_in[4];
    const int*   e1  = (const int*)d_in[5];

    int n  = in_sizes[0] / DIM;
    int nE = in_sizes[4] / 2;
    float* out = (float*)d_out;

    void *p_emb1_v, *p_Y_v;
    cudaGetSymbolAddress(&p_emb1_v, g_emb1);
    cudaGetSymbolAddress(&p_Y_v, g_Y);
    float* p_emb1 = (float*)p_emb1_v;
    float* p_Y    = (float*)p_Y_v;

    cudaFuncSetAttribute(gemm_kernel, cudaFuncAttributeMaxDynamicSharedMemorySize,
                         GEMM_SMEM_BYTES);

    int nb = (n + 511) / 512;
    int gemm_blocks = (n + 127) / 128;
    int agg_blocks = (n * 32 + 255) / 256;

    // gemm1 at launch slot #4 (the slot ncu captures) for profiling.
    zero_counts_kernel<<<(2 * NMAX + 255) / 256, 256>>>();                 // 1
    hist_kernel<<<(2 * nE + 255) / 256, 256>>>(e0, e1, nE);                // 2
    convert_theta_kernel<<<(3 * 12 * 8 * 32 + 255) / 256, 256>>>(t1, t2, t3); // 3
    gemm_kernel<<<gemm_blocks, 512, GEMM_SMEM_BYTES>>>(emb, p_emb1, p_Y, n); // 4
    dim3 gscan(nb, 2);
    scan_partial_kernel<<<gscan, 512>>>(n);                                // 5
    dim3 goff((n + 255) / 256, 2);
    add_offsets_kernel<<<goff, 256>>>(n, nb);                              // 6
    fill_kernel<<<(2 * nE + 255) / 256, 256>>>(e0, e1, nE);                // 7
    agg_kernel<<<agg_blocks, 256>>>(p_Y, p_emb1, n);                       // 8
    gemm_kernel<<<gemm_blocks, 512, GEMM_SMEM_BYTES>>>(p_emb1, out, p_Y, n); // 9
    agg_kernel<<<agg_blocks, 256>>>(p_Y, out, n);                          // 10
}

// round 13
// speedup vs baseline: 1.1003x; 1.0222x over previous
#include <cuda_runtime.h>
#include <cuda_bf16.h>
#include <cstdint>

// ---------------------------------------------------------------------------
// IterativeEmbeddingModel: 2 iterations of
//   emb <- concat(emb@T1, seg_sum(emb[col],row)@T2, seg_sum_anti(...)@T3)
// R13 (consolidation on R8 champion; R9-R12 bracketed the GEMM design space):
//  - GEMM: exact R8 body (m16xn32 warps, 512 thr, BM=128) + double-buffered
//    B fills via cp.async (theta0 fill hidden behind A-convert, theta1/2
//    hidden behind prior theta's compute). smem 204.8KB, syncs 6 -> 4.
//  - agg: edge/anti lists split across blockIdx.y (2x warp parallelism).
//  - zero_counts fused into convert_theta (prep_kernel), -1 launch.
//  Split-bf16 3-term math (rel_err ~6e-6, tolerance 1e-3).
// ---------------------------------------------------------------------------

#define NMAX 50000
#define EMAX 400000
#define DIM  192
#define PP   64

// Scratch (device globals; no allocation APIs allowed)
__device__ int      g_count[2 * NMAX];
__device__ int      g_cursor[2 * NMAX];
__device__ int      g_rowstart[2 * (NMAX + 1)];
__device__ int      g_blocksum[2 * 128];
__device__ int      g_cols[2 * EMAX];
__device__ float    g_emb1[(size_t)NMAX * DIM];   // iteration-1 output
__device__ float    g_Y[(size_t)NMAX * 128];      // [Y2 | Y3] per row
__device__ uint32_t g_Bh32[3 * 64 * 96];          // thetas bf16-hi, [t][n][k2]
__device__ uint32_t g_Bl32[3 * 64 * 96];          // thetas bf16-lo

__device__ __forceinline__ uint32_t smem_to_u32(const void* p) {
    uint32_t a;
    asm("{ .reg .u64 t; cvta.to.shared.u64 t, %1; cvt.u32.u64 %0, t; }"
        : "=r"(a) : "l"(p));
    return a;
}

// ---- prep: zero counts + convert thetas to bf16 hi/lo (one kernel) --------
__global__ void prep_kernel(const float* __restrict__ t1,
                            const float* __restrict__ t2,
                            const float* __restrict__ t3) {
    int i = blockIdx.x * blockDim.x + threadIdx.x;
    if (i < 2 * NMAX) g_count[i] = 0;
    if (i < 3 * 64 * 96) {
        int tt = i / 6144;
        int rem = i % 6144;
        int nn = rem / 96;
        int k2 = rem % 96;
        const float* T = (tt == 0) ? t1 : (tt == 1) ? t2 : t3;
        float x0 = T[(size_t)(2 * k2) * 64 + nn];
        float x1 = T[(size_t)(2 * k2 + 1) * 64 + nn];
        __nv_bfloat162 hh = __floats2bfloat162_rn(x0, x1);
        float r0 = x0 - __low2float(hh);
        float r1 = x1 - __high2float(hh);
        __nv_bfloat162 ll = __floats2bfloat162_rn(r0, r1);
        g_Bh32[i] = *(uint32_t*)&hh;
        g_Bl32[i] = *(uint32_t*)&ll;
    }
}

// ---- CSR build ------------------------------------------------------------
__global__ void hist_kernel(const int* __restrict__ e0, const int* __restrict__ e1, int nE) {
    int i = blockIdx.x * blockDim.x + threadIdx.x;
    if (i >= 2 * nE) return;
    int l = (i < nE) ? 0 : 1;
    const int* p = l ? e1 : e0;
    int e = l ? (i - nE) : i;
    int d = p[e];
    atomicAdd(&g_count[l * NMAX + d], 1);
}

__global__ void scan_partial_kernel(int n) {
    __shared__ int warp_sums[16];
    int l = blockIdx.y;
    int i = blockIdx.x * 512 + threadIdx.x;
    int lane = threadIdx.x & 31;
    int w = threadIdx.x >> 5;
    int v = (i < n) ? g_count[l * NMAX + i] : 0;
    int s = v;
#pragma unroll
    for (int o = 1; o < 32; o <<= 1) {
        int t = __shfl_up_sync(0xFFFFFFFFu, s, o);
        if (lane >= o) s += t;
    }
    if (lane == 31) warp_sums[w] = s;
    __syncthreads();
    if (w == 0) {
        int ws = (lane < 16) ? warp_sums[lane] : 0;
#pragma unroll
        for (int o = 1; o < 16; o <<= 1) {
            int t = __shfl_up_sync(0xFFFFFFFFu, ws, o);
            if (lane >= o) ws += t;
        }
        if (lane < 16) warp_sums[lane] = ws;
    }
    __syncthreads();
    int base = (w > 0) ? warp_sums[w - 1] : 0;
    if (i < n) g_rowstart[l * (NMAX + 1) + i] = base + s - v;
    if (threadIdx.x == 511) g_blocksum[l * 128 + blockIdx.x] = base + s;
}

__global__ void add_offsets_kernel(int n, int nb) {
    int l = blockIdx.y;
    int i = blockIdx.x * blockDim.x + threadIdx.x;
    __shared__ int sP;
    if (threadIdx.x < 32) {
        int myblk = blockIdx.x >> 1;
        int s = 0;
        for (int b = threadIdx.x; b < myblk; b += 32) s += g_blocksum[l * 128 + b];
#pragma unroll
        for (int o = 16; o; o >>= 1) s += __shfl_xor_sync(0xFFFFFFFFu, s, o);
        if (threadIdx.x == 0) sP = s;
    }
    if (blockIdx.x == 0 && threadIdx.x >= 32 && threadIdx.x < 64) {
        int lane = threadIdx.x - 32;
        int s = 0;
        for (int b = lane; b < nb; b += 32) s += g_blocksum[l * 128 + b];
#pragma unroll
        for (int o = 16; o; o >>= 1) s += __shfl_xor_sync(0xFFFFFFFFu, s, o);
        if (lane == 0) g_rowstart[l * (NMAX + 1) + n] = s;
    }
    __syncthreads();
    if (i < n) {
        g_rowstart[l * (NMAX + 1) + i] += sP;
        g_cursor[l * NMAX + i] = 0;
    }
}

__global__ void fill_kernel(const int* __restrict__ e0, const int* __restrict__ e1, int nE) {
    int i = blockIdx.x * blockDim.x + threadIdx.x;
    if (i >= 2 * nE) return;
    int l = (i < nE) ? 0 : 1;
    const int* p = l ? e1 : e0;
    int e = l ? (i - nE) : i;
    int d = p[e];
    int c = p[nE + e];
    int pos = g_rowstart[l * (NMAX + 1) + d] + atomicAdd(&g_cursor[l * NMAX + d], 1);
    g_cols[l * EMAX + pos] = c;
}

// ---- mma.sync GEMM (R8 body + cp.async double-buffered B) -----------------
// Per CTA: rows [rowBase, rowBase+128), all 192 output cols (3 thetas).
// 512 threads / 16 warps: warp (w&7) -> m16 row group, (w>>3) -> n half (32).
// smem: Ah[128][200] | Al[128][200] | Bbuf0{h,l} | Bbuf1{h,l}  (bf16, str 200)
#define A_STRIDE 200
#define OFF_AH 0
#define OFF_AL 51200
#define OFF_B0 102400
#define OFF_B1 153600
#define B_HL   25600      // lo half offset within a B buffer
#define GEMM_SMEM_BYTES 204800

#define MMA(C, A0, A1, A2, A3, B0, B1)                                  \
    asm("mma.sync.aligned.m16n8k16.row.col.f32.bf16.bf16.f32 "          \
        "{%0,%1,%2,%3}, {%4,%5,%6,%7}, {%8,%9}, {%0,%1,%2,%3};"         \
        : "+f"(C.x), "+f"(C.y), "+f"(C.z), "+f"(C.w)                    \
        : "r"(A0), "r"(A1), "r"(A2), "r"(A3), "r"(B0), "r"(B1))

#define LDMX4(R0, R1, R2, R3, ADDR)                                     \
    asm volatile("ldmatrix.sync.aligned.m8n8.x4.shared.b16 "            \
                 "{%0,%1,%2,%3}, [%4];"                                 \
                 : "=r"(R0), "=r"(R1), "=r"(R2), "=r"(R3) : "r"(ADDR))

// Fill one B buffer (theta TT) with cp.async: 64 rows x 24 16B-chunks, hi+lo.
#define CP_FILL(TT, DSTBASE) do {                                             \
    const char* srcH = (const char*)(g_Bh32 + (TT) * 6144);                   \
    const char* srcL = (const char*)(g_Bl32 + (TT) * 6144);                   \
    uint32_t dstH = (DSTBASE);                                                \
    uint32_t dstL = dstH + B_HL;                                              \
    for (int f = tid; f < 1536; f += 512) {                                   \
        int r = f / 24, ck = f % 24;                                          \
        uint32_t doff = (uint32_t)(r * 400 + ck * 16);                        \
        size_t soff = (size_t)r * 384 + (size_t)ck * 16;                      \
        asm volatile("cp.async.cg.shared.global [%0], [%1], 16;"              \
            :: "r"(dstH + doff), "l"(srcH + soff));                           \
        asm volatile("cp.async.cg.shared.global [%0], [%1], 16;"              \
            :: "r"(dstL + doff), "l"(srcL + soff));                           \
    }                                                                         \
    asm volatile("cp.async.commit_group;" ::: "memory");                      \
} while (0)

__global__ __launch_bounds__(512, 1)
void gemm_kernel(const float* __restrict__ A,
                 float* __restrict__ dst,   // n x 192 (theta0 -> cols 0:64)
                 float* __restrict__ Y,     // n x 128 (theta1|theta2)
                 int n)
{
    extern __shared__ char smem[];
    uint32_t* Ah32 = (uint32_t*)(smem + OFF_AH);
    uint32_t* Al32 = (uint32_t*)(smem + OFF_AL);

    const int tid = threadIdx.x;
    const int w = tid >> 5;
    const int lane = tid & 31;
    const int mw = w & 7;          // m16 row-group index
    const int nh = w >> 3;         // n half (0: cols 0-31, 1: cols 32-63)
    const int q = lane & 3;
    const int rowBase = blockIdx.x * 128;
    const uint32_t sb = smem_to_u32(smem);

    // ---- Prefetch theta0 B into buffer 0 (overlaps A conversion) ----
    CP_FILL(0, sb + OFF_B0);

    // ---- Convert A rows to bf16 hi/lo in smem (coalesced, conflict-free) --
    for (int f = tid; f < 128 * 96; f += 512) {
        int r = f / 96, k2 = f % 96;
        int gr = rowBase + r;
        float2 v = make_float2(0.f, 0.f);
        if (gr < n) v = *(const float2*)(A + (size_t)gr * DIM + 2 * k2);
        __nv_bfloat162 hh = __floats2bfloat162_rn(v.x, v.y);
        float r0 = v.x - __low2float(hh);
        float r1 = v.y - __high2float(hh);
        __nv_bfloat162 ll = __floats2bfloat162_rn(r0, r1);
        Ah32[r * 100 + k2] = *(uint32_t*)&hh;
        Al32[r * 100 + k2] = *(uint32_t*)&ll;
    }

    // ---- per-lane ldmatrix base addresses ----
    const int raA = (lane & 7) + ((lane >> 3) & 1) * 8;
    const int kaA = ((lane >> 4) & 1) * 8;
    uint32_t aAh = sb + OFF_AH + (uint32_t)((mw * 16 + raA) * A_STRIDE + kaA) * 2;
    uint32_t aAl = aAh + (OFF_AL - OFF_AH);
    const int rbB = (lane & 7) + ((lane >> 4) & 1) * 8;
    const int kbB = ((lane >> 3) & 1) * 8;
    const uint32_t bOffH = (uint32_t)((nh * 32 + rbB) * A_STRIDE + kbB) * 2;

    const int row0 = rowBase + mw * 16 + (lane >> 2);
    const int row1 = row0 + 8;

    asm volatile("cp.async.wait_group 0;" ::: "memory");
    __syncthreads();   // A + theta0 B visible

#pragma unroll
    for (int tt = 0; tt < 3; ++tt) {
        if (tt == 0) {
            CP_FILL(1, sb + OFF_B1);                 // theta1 overlaps theta0
        } else if (tt == 1) {
            CP_FILL(2, sb + OFF_B0);                 // theta2 overlaps theta1
            asm volatile("cp.async.wait_group 1;" ::: "memory");
            __syncthreads();                          // theta1 visible
        } else {
            asm volatile("cp.async.wait_group 0;" ::: "memory");
            __syncthreads();                          // theta2 visible
        }

        const uint32_t bbase = sb + ((tt & 1) ? OFF_B1 : OFF_B0);
        uint32_t aB0h = bbase + bOffH;
        uint32_t aB1h = aB0h + 16 * A_STRIDE * 2;
        uint32_t aB0l = aB0h + B_HL;
        uint32_t aB1l = aB1h + B_HL;

        float4 c0 = make_float4(0.f, 0.f, 0.f, 0.f), c1 = c0, c2 = c0, c3 = c0;

#pragma unroll 2
        for (int ks = 0; ks < 12; ++ks) {
            const uint32_t ko = (uint32_t)ks * 32;   // 16 bf16 = 32 bytes
            uint32_t ah0, ah1, ah2, ah3, al0, al1, al2, al3;
            LDMX4(ah0, ah1, ah2, ah3, aAh + ko);
            LDMX4(al0, al1, al2, al3, aAl + ko);
            uint32_t b0h0, b0h1, b1h0, b1h1;
            LDMX4(b0h0, b0h1, b1h0, b1h1, aB0h + ko);
            uint32_t b2h0, b2h1, b3h0, b3h1;
            LDMX4(b2h0, b2h1, b3h0, b3h1, aB1h + ko);
            uint32_t b0l0, b0l1, b1l0, b1l1;
            LDMX4(b0l0, b0l1, b1l0, b1l1, aB0l + ko);
            uint32_t b2l0, b2l1, b3l0, b3l1;
            LDMX4(b2l0, b2l1, b3l0, b3l1, aB1l + ko);

            MMA(c0, ah0, ah1, ah2, ah3, b0h0, b0h1);
            MMA(c1, ah0, ah1, ah2, ah3, b1h0, b1h1);
            MMA(c2, ah0, ah1, ah2, ah3, b2h0, b2h1);
            MMA(c3, ah0, ah1, ah2, ah3, b3h0, b3h1);
            MMA(c0, ah0, ah1, ah2, ah3, b0l0, b0l1);
            MMA(c1, ah0, ah1, ah2, ah3, b1l0, b1l1);
            MMA(c2, ah0, ah1, ah2, ah3, b2l0, b2l1);
            MMA(c3, ah0, ah1, ah2, ah3, b3l0, b3l1);
            MMA(c0, al0, al1, al2, al3, b0h0, b0h1);
            MMA(c1, al0, al1, al2, al3, b1h0, b1h1);
            MMA(c2, al0, al1, al2, al3, b2h0, b2h1);
            MMA(c3, al0, al1, al2, al3, b3h0, b3h1);
        }

        // ---- Epilogue for this theta ----
        float* outp = (tt == 0) ? dst : Y;
        const int ostr = (tt == 0) ? DIM : 128;
        const int cb = ((tt == 2) ? 64 : 0) + nh * 32;
#define ST_TILE(C, J)                                                         \
        {                                                                     \
            int col = cb + (J) * 8 + 2 * q;                                   \
            if (row0 < n)                                                     \
                *(float2*)(outp + (size_t)row0 * ostr + col) =                \
                    make_float2(C.x, C.y);                                    \
            if (row1 < n)                                                     \
                *(float2*)(outp + (size_t)row1 * ostr + col) =                \
                    make_float2(C.z, C.w);                                    \
        }
        ST_TILE(c0, 0) ST_TILE(c1, 1) ST_TILE(c2, 2) ST_TILE(c3, 3)
#undef ST_TILE

        if (tt == 0) __syncthreads();   // buffer0 readers done before theta2 fill lands
    }
}

// ---- Aggregation: warp per (node, list), atomic-free CSR gather -----------
__global__ void agg_kernel(const float* __restrict__ Y, float* __restrict__ dst, int n)
{
    int gw = (blockIdx.x * blockDim.x + threadIdx.x) >> 5;
    int lane = threadIdx.x & 31;
    int l = blockIdx.y;
    if (gw >= n) return;
    const int* rs = g_rowstart + l * (NMAX + 1);
    const int* cs = g_cols + l * EMAX;
    int s = __ldg(rs + gw);
    int e = __ldg(rs + gw + 1);
    const float* Yb = Y + l * 64 + lane * 2;
    float ax = 0.f, ay = 0.f;
    int j = s;
    for (; j + 4 <= e; j += 4) {
        int c0 = cs[j], c1 = cs[j + 1], c2 = cs[j + 2], c3 = cs[j + 3];
        float2 v0 = *(const float2*)(Yb + (size_t)c0 * 128);
        float2 v1 = *(const float2*)(Yb + (size_t)c1 * 128);
        float2 v2 = *(const float2*)(Yb + (size_t)c2 * 128);
        float2 v3 = *(const float2*)(Yb + (size_t)c3 * 128);
        ax += (v0.x + v1.x) + (v2.x + v3.x);
        ay += (v0.y + v1.y) + (v2.y + v3.y);
    }
    for (; j < e; ++j) {
        float2 v = *(const float2*)(Yb + (size_t)cs[j] * 128);
        ax += v.x; ay += v.y;
    }
    *(float2*)(dst + (size_t)gw * DIM + 64 + l * 64 + lane * 2) =
        make_float2(ax, ay);
}

// ---------------------------------------------------------------------------
extern "C" void kernel_launch(void* const* d_in, const int* in_sizes, int n_in,
                              void* d_out, int out_size)
{
    const float* emb = (const float*)d_in[0];
    const float* t1  = (const float*)d_in[1];
    const float* t2  = (const float*)d_in[2];
    const float* t3  = (const float*)d_in[3];
    const int*   e0  = (const int*)d_in[4];
    const int*   e1  = (const int*)d_in[5];

    int n  = in_sizes[0] / DIM;
    int nE = in_sizes[4] / 2;
    float* out = (float*)d_out;

    void *p_emb1_v, *p_Y_v;
    cudaGetSymbolAddress(&p_emb1_v, g_emb1);
    cudaGetSymbolAddress(&p_Y_v, g_Y);
    float* p_emb1 = (float*)p_emb1_v;
    float* p_Y    = (float*)p_Y_v;

    cudaFuncSetAttribute(gemm_kernel, cudaFuncAttributeMaxDynamicSharedMemorySize,
                         GEMM_SMEM_BYTES);

    int nb = (n + 511) / 512;
    int gemm_blocks = (n + 127) / 128;
    dim3 agg_grid((n * 32 + 255) / 256, 2);

    // gemm1 at launch slot #4 (the slot ncu captures) for profiling.
    prep_kernel<<<(2 * NMAX + 255) / 256, 256>>>(t1, t2, t3);              // 1
    hist_kernel<<<(2 * nE + 255) / 256, 256>>>(e0, e1, nE);                // 2
    dim3 gscan(nb, 2);
    scan_partial_kernel<<<gscan, 512>>>(n);                                // 3
    gemm_kernel<<<gemm_blocks, 512, GEMM_SMEM_BYTES>>>(emb, p_emb1, p_Y, n); // 4
    dim3 goff((n + 255) / 256, 2);
    add_offsets_kernel<<<goff, 256>>>(n, nb);                              // 5
    fill_kernel<<<(2 * nE + 255) / 256, 256>>>(e0, e1, nE);                // 6
    agg_kernel<<<agg_grid, 256>>>(p_Y, p_emb1, n);                         // 7
    gemm_kernel<<<gemm_blocks, 512, GEMM_SMEM_BYTES>>>(p_emb1, out, p_Y, n); // 8
    agg_kernel<<<agg_grid, 256>>>(p_Y, out, n);                            // 9
}